// round 2
// baseline (speedup 1.0000x reference)
#include <cuda_runtime.h>
#include <math.h>

#define S_LEN 2048
#define NB 2
#define NH 16
#define HD 64
#define DM 1024
#define MROWS (NB * S_LEN)   // 4096

// Scratch: projected Q/K/V in [B,H,S,64] layout, attention output in [B,S,D]
__device__ float g_qp[NB * NH * S_LEN * HD];
__device__ float g_kp[NB * NH * S_LEN * HD];
__device__ float g_vp[NB * NH * S_LEN * HD];
__device__ float g_ao[MROWS * DM];

// ---------------------------------------------------------------------------
// C = A[ M x 1024 ] @ W[ 1024 x 1024 ] + bias, 64x64 block, 4x8 per thread.
// sel 0/1/2: scatter into g_qp/g_kp/g_vp as [B,H,S,64]. sel 3: A=g_ao, C=Cout.
// ---------------------------------------------------------------------------
__global__ __launch_bounds__(128) void gemm_bias_kernel(
    const float* __restrict__ A_in, const float* __restrict__ W,
    const float* __restrict__ bias, float* __restrict__ Cout, int sel)
{
    __shared__ float As[16][64];   // [k][m] (transposed)
    __shared__ float Bs[16][64];   // [k][n]

    const float* A = (sel == 3) ? g_ao : A_in;
    float* Cdst;
    if (sel == 0) Cdst = g_qp;
    else if (sel == 1) Cdst = g_kp;
    else if (sel == 2) Cdst = g_vp;
    else Cdst = Cout;

    const int tid = threadIdx.x;          // 128 threads
    const int ty = tid >> 3;              // 0..15
    const int tx = tid & 7;               // 0..7
    const int m0 = blockIdx.x * 64;
    const int n0 = blockIdx.y * 64;

    float acc[4][8];
#pragma unroll
    for (int i = 0; i < 4; i++)
#pragma unroll
        for (int j = 0; j < 8; j++) acc[i][j] = 0.f;

    for (int k0 = 0; k0 < DM; k0 += 16) {
        // A tile 64x16 -> As[k][m] (transposed store)
        {
            int r = tid >> 2;             // 0..31
            int c = (tid & 3) << 2;       // 0,4,8,12
#pragma unroll
            for (int rr = 0; rr < 2; rr++) {
                float4 a = *(const float4*)(A + (size_t)(m0 + r + rr * 32) * DM + k0 + c);
                As[c + 0][r + rr * 32] = a.x;
                As[c + 1][r + rr * 32] = a.y;
                As[c + 2][r + rr * 32] = a.z;
                As[c + 3][r + rr * 32] = a.w;
            }
        }
        // W tile 16x64 -> Bs[k][n]
        {
            int r = tid >> 4;             // 0..7
            int c = (tid & 15) << 2;      // 0..60
#pragma unroll
            for (int rr = 0; rr < 2; rr++) {
                *(float4*)&Bs[r + rr * 8][c] =
                    *(const float4*)(W + (size_t)(k0 + r + rr * 8) * DM + n0 + c);
            }
        }
        __syncthreads();

#pragma unroll
        for (int kk = 0; kk < 16; kk++) {
            float a4[4], b8[8];
            *(float4*)a4       = *(float4*)&As[kk][ty << 2];
            *(float4*)b8       = *(float4*)&Bs[kk][tx << 3];
            *(float4*)(b8 + 4) = *(float4*)&Bs[kk][(tx << 3) + 4];
#pragma unroll
            for (int i = 0; i < 4; i++)
#pragma unroll
                for (int j = 0; j < 8; j++)
                    acc[i][j] += a4[i] * b8[j];
        }
        __syncthreads();
    }

    // epilogue
#pragma unroll
    for (int i = 0; i < 4; i++) {
        int m = m0 + (ty << 2) + i;
        float o[8];
#pragma unroll
        for (int j = 0; j < 8; j++) o[j] = acc[i][j] + bias[n0 + (tx << 3) + j];

        if (sel < 3) {
            int b = m >> 11;                 // m / 2048
            int s = m & (S_LEN - 1);
            int h = n0 >> 6;                 // 64-wide n-tile == one head
            float* dst = Cdst + ((size_t)((b * NH + h) * S_LEN + s)) * HD + (tx << 3);
            *(float4*)dst       = *(float4*)o;
            *(float4*)(dst + 4) = *(float4*)(o + 4);
        } else {
            float* dst = Cdst + (size_t)m * DM + n0 + (tx << 3);
            *(float4*)dst       = *(float4*)o;
            *(float4*)(dst + 4) = *(float4*)(o + 4);
        }
    }
}

// ---------------------------------------------------------------------------
// Flash-style attention, fp32. 64 queries x 64 keys per tile, 128 threads.
// Faithful soft mask: future keys get -ln2 added to scaled logits.
// ---------------------------------------------------------------------------
__global__ __launch_bounds__(128) void attn_kernel(const int* __restrict__ use_mask_p)
{
    extern __shared__ float sm[];
    const int STR = 68;                    // padded row stride (16B-aligned)
    float* Qs = sm;
    float* Ks = sm + 64 * STR;
    float* Vs = sm + 2 * 64 * STR;
    float* Ps = sm + 3 * 64 * STR;

    const int tid = threadIdx.x;
    const int ty = tid >> 3;               // 0..15 -> 4 query rows each
    const int tx = tid & 7;                // 0..7  -> 8 cols each
    const int bh = blockIdx.y;             // b*16 + h
    const int q0 = blockIdx.x << 6;

    const float* Qg = g_qp + (size_t)bh * S_LEN * HD;
    const float* Kg = g_kp + (size_t)bh * S_LEN * HD;
    const float* Vg = g_vp + (size_t)bh * S_LEN * HD;
    const int use_mask = *use_mask_p;
    const float LN2 = 0.69314718055994530942f;

    // Load Q tile (64x64)
#pragma unroll
    for (int it = 0; it < 8; it++) {
        int idx = (it << 7) + tid;         // 0..1023 float4 slots
        int r = idx >> 4;
        int c = (idx & 15) << 2;
        *(float4*)&Qs[r * STR + c] = *(const float4*)&Qg[(size_t)(q0 + r) * HD + c];
    }

    float m_i[4], l_i[4], acc[4][8];
#pragma unroll
    for (int i = 0; i < 4; i++) {
        m_i[i] = -1e30f;
        l_i[i] = 0.f;
#pragma unroll
        for (int j = 0; j < 8; j++) acc[i][j] = 0.f;
    }

    for (int kt = 0; kt < 32; kt++) {
        const int k0 = kt << 6;
        // Load K,V tiles
#pragma unroll
        for (int it = 0; it < 8; it++) {
            int idx = (it << 7) + tid;
            int r = idx >> 4;
            int c = (idx & 15) << 2;
            *(float4*)&Ks[r * STR + c] = *(const float4*)&Kg[(size_t)(k0 + r) * HD + c];
            *(float4*)&Vs[r * STR + c] = *(const float4*)&Vg[(size_t)(k0 + r) * HD + c];
        }
        __syncthreads();

        // scores S = Q @ K^T
        float s[4][8];
#pragma unroll
        for (int i = 0; i < 4; i++)
#pragma unroll
            for (int j = 0; j < 8; j++) s[i][j] = 0.f;

#pragma unroll
        for (int d = 0; d < 64; d += 4) {
            float q4[4][4];
#pragma unroll
            for (int i = 0; i < 4; i++)
                *(float4*)q4[i] = *(float4*)&Qs[((ty << 2) + i) * STR + d];
#pragma unroll
            for (int j = 0; j < 8; j++) {
                float k4[4];
                *(float4*)k4 = *(float4*)&Ks[((tx << 3) + j) * STR + d];
#pragma unroll
                for (int i = 0; i < 4; i++)
                    s[i][j] += q4[i][0] * k4[0] + q4[i][1] * k4[1]
                             + q4[i][2] * k4[2] + q4[i][3] * k4[3];
            }
        }

        // online softmax with -ln2 soft mask on future keys
#pragma unroll
        for (int i = 0; i < 4; i++) {
            int qi = q0 + (ty << 2) + i;
            float mx = -1e30f;
#pragma unroll
            for (int j = 0; j < 8; j++) {
                float adj = s[i][j] * 0.125f;
                if (use_mask && (k0 + (tx << 3) + j) > qi) adj -= LN2;
                s[i][j] = adj;
                mx = fmaxf(mx, adj);
            }
            mx = fmaxf(mx, __shfl_xor_sync(0xffffffffu, mx, 1));
            mx = fmaxf(mx, __shfl_xor_sync(0xffffffffu, mx, 2));
            mx = fmaxf(mx, __shfl_xor_sync(0xffffffffu, mx, 4));
            float mnew  = fmaxf(m_i[i], mx);
            float alpha = __expf(m_i[i] - mnew);
            float rs = 0.f;
#pragma unroll
            for (int j = 0; j < 8; j++) {
                float p = __expf(s[i][j] - mnew);
                Ps[((ty << 2) + i) * STR + (tx << 3) + j] = p;
                rs += p;
            }
            rs += __shfl_xor_sync(0xffffffffu, rs, 1);
            rs += __shfl_xor_sync(0xffffffffu, rs, 2);
            rs += __shfl_xor_sync(0xffffffffu, rs, 4);
            l_i[i] = l_i[i] * alpha + rs;
            m_i[i] = mnew;
#pragma unroll
            for (int j = 0; j < 8; j++) acc[i][j] *= alpha;
        }
        __syncthreads();   // Ps complete

        // O += P @ V
#pragma unroll
        for (int k = 0; k < 64; k += 4) {
            float p4[4][4];
#pragma unroll
            for (int i = 0; i < 4; i++)
                *(float4*)p4[i] = *(float4*)&Ps[((ty << 2) + i) * STR + k];
#pragma unroll
            for (int kk = 0; kk < 4; kk++) {
                float v8[8];
                *(float4*)v8       = *(float4*)&Vs[(k + kk) * STR + (tx << 3)];
                *(float4*)(v8 + 4) = *(float4*)&Vs[(k + kk) * STR + (tx << 3) + 4];
#pragma unroll
                for (int i = 0; i < 4; i++)
#pragma unroll
                    for (int j = 0; j < 8; j++)
                        acc[i][j] += p4[i][kk] * v8[j];
            }
        }
        __syncthreads();   // done with Ks/Vs/Ps before next tile overwrites
    }

    // normalize and write to [B,S,D] scratch
    const int b = bh >> 4, h = bh & 15;
#pragma unroll
    for (int i = 0; i < 4; i++) {
        int srow = q0 + (ty << 2) + i;
        float inv = 1.0f / l_i[i];
        float o[8];
#pragma unroll
        for (int j = 0; j < 8; j++) o[j] = acc[i][j] * inv;
        float* dst = g_ao + ((size_t)(b * S_LEN + srow)) * DM + (h << 6) + (tx << 3);
        *(float4*)dst       = *(float4*)o;
        *(float4*)(dst + 4) = *(float4*)(o + 4);
    }
}

// ---------------------------------------------------------------------------
extern "C" void kernel_launch(void* const* d_in, const int* in_sizes, int n_in,
                              void* d_out, int out_size)
{
    (void)in_sizes; (void)n_in; (void)out_size;
    const float* q  = (const float*)d_in[0];
    const float* k  = (const float*)d_in[1];
    const float* v  = (const float*)d_in[2];
    const float* Wq = (const float*)d_in[3];
    const float* bq = (const float*)d_in[4];
    const float* Wk = (const float*)d_in[5];
    const float* bk = (const float*)d_in[6];
    const float* Wv = (const float*)d_in[7];
    const float* bv = (const float*)d_in[8];
    const float* Wo = (const float*)d_in[9];
    const float* bo = (const float*)d_in[10];
    const int* use_mask = (const int*)d_in[11];
    float* out = (float*)d_out;

    const int attn_smem = 4 * 64 * 68 * (int)sizeof(float);   // 69632 B
    cudaFuncSetAttribute(attn_kernel, cudaFuncAttributeMaxDynamicSharedMemorySize, attn_smem);

    dim3 gg(MROWS / 64, DM / 64);   // (64, 16)
    gemm_bias_kernel<<<gg, 128>>>(q, Wq, bq, nullptr, 0);
    gemm_bias_kernel<<<gg, 128>>>(k, Wk, bk, nullptr, 1);
    gemm_bias_kernel<<<gg, 128>>>(v, Wv, bv, nullptr, 2);

    attn_kernel<<<dim3(S_LEN / 64, NB * NH), 128, attn_smem>>>(use_mask);

    gemm_bias_kernel<<<gg, 128>>>(nullptr, Wo, bo, out, 3);
}

// round 6
// speedup vs baseline: 2.4300x; 2.4300x over previous
#include <cuda_runtime.h>
#include <cuda_bf16.h>
#include <cstdint>

#define S_LEN 2048
#define NB 2
#define NH 16
#define HD 64
#define DM 1024
#define MROWS (NB * S_LEN)   // 4096

// fp32 attention output (input to out-proj GEMM)
__device__ float g_ao[MROWS * DM];
// bf16 hi/lo splits of projected Q/K/V in [B,H,S,64] layout
__device__ __nv_bfloat16 g_qh[NB*NH*S_LEN*HD], g_ql[NB*NH*S_LEN*HD];
__device__ __nv_bfloat16 g_kh[NB*NH*S_LEN*HD], g_kl[NB*NH*S_LEN*HD];
__device__ __nv_bfloat16 g_vh[NB*NH*S_LEN*HD], g_vl[NB*NH*S_LEN*HD];

// ===========================================================================
// arch-neutral PTX helpers (sm_80-class: ldmatrix / mma.sync / cp.async)
// ===========================================================================
__device__ __forceinline__ uint32_t smem_u32(const void* p) {
    uint32_t a;
    asm("{ .reg .u64 t; cvta.to.shared.u64 t, %1; cvt.u32.u64 %0, t; }" : "=r"(a) : "l"(p));
    return a;
}
__device__ __forceinline__ void ldsm4(uint32_t r[4], uint32_t a) {
    asm volatile("ldmatrix.sync.aligned.m8n8.x4.shared.b16 {%0,%1,%2,%3}, [%4];"
                 : "=r"(r[0]), "=r"(r[1]), "=r"(r[2]), "=r"(r[3]) : "r"(a));
}
__device__ __forceinline__ void ldsm4t(uint32_t r[4], uint32_t a) {
    asm volatile("ldmatrix.sync.aligned.m8n8.x4.trans.shared.b16 {%0,%1,%2,%3}, [%4];"
                 : "=r"(r[0]), "=r"(r[1]), "=r"(r[2]), "=r"(r[3]) : "r"(a));
}
__device__ __forceinline__ void mma_bf16(float c[4], const uint32_t a[4], const uint32_t b[2]) {
    asm volatile("mma.sync.aligned.m16n8k16.row.col.f32.bf16.bf16.f32 "
                 "{%0,%1,%2,%3}, {%4,%5,%6,%7}, {%8,%9}, {%0,%1,%2,%3};"
                 : "+f"(c[0]), "+f"(c[1]), "+f"(c[2]), "+f"(c[3])
                 : "r"(a[0]), "r"(a[1]), "r"(a[2]), "r"(a[3]), "r"(b[0]), "r"(b[1]));
}
__device__ __forceinline__ void cp16(uint32_t dst, const void* src) {
    asm volatile("cp.async.cg.shared.global [%0], [%1], 16;" :: "r"(dst), "l"(src));
}
#define CP_COMMIT() asm volatile("cp.async.commit_group;" ::: "memory")
#define CP_WAIT0()  asm volatile("cp.async.wait_group 0;" ::: "memory")
#define CP_WAIT1()  asm volatile("cp.async.wait_group 1;" ::: "memory")

// pack2(x,y): .b32 with bf16(x) in low half, bf16(y) in high half
__device__ __forceinline__ uint32_t pack2(float x, float y) {
    uint32_t r;
    asm("cvt.rn.bf16x2.f32 %0, %1, %2;" : "=r"(r) : "f"(y), "f"(x));
    return r;
}
__device__ __forceinline__ float2 unpack2(uint32_t r) {
    __nv_bfloat162 b = *reinterpret_cast<__nv_bfloat162*>(&r);
    return __bfloat1622float2(b);   // .x = low half
}

// ===========================================================================
// SIMT GEMM: C = A @ W + bias.  sel 0/1/2 -> bf16 hi/lo Q/K/V [B,H,S,64];
// sel 3 -> A=g_ao, C=Cout fp32.
// ===========================================================================
__global__ __launch_bounds__(128) void gemm_bias_kernel(
    const float* __restrict__ A_in, const float* __restrict__ W,
    const float* __restrict__ bias, float* __restrict__ Cout, int sel)
{
    __shared__ float As[16][64];
    __shared__ float Bs[16][64];

    const float* A = (sel == 3) ? g_ao : A_in;
    __nv_bfloat16 *Dh = nullptr, *Dl = nullptr;
    if (sel == 0) { Dh = g_qh; Dl = g_ql; }
    else if (sel == 1) { Dh = g_kh; Dl = g_kl; }
    else if (sel == 2) { Dh = g_vh; Dl = g_vl; }

    const int tid = threadIdx.x;
    const int ty = tid >> 3, tx = tid & 7;
    const int m0 = blockIdx.x * 64, n0 = blockIdx.y * 64;

    float acc[4][8];
#pragma unroll
    for (int i = 0; i < 4; i++)
#pragma unroll
        for (int j = 0; j < 8; j++) acc[i][j] = 0.f;

    for (int k0 = 0; k0 < DM; k0 += 16) {
        {
            int r = tid >> 2, c = (tid & 3) << 2;
#pragma unroll
            for (int rr = 0; rr < 2; rr++) {
                float4 a = *(const float4*)(A + (size_t)(m0 + r + rr * 32) * DM + k0 + c);
                As[c + 0][r + rr * 32] = a.x; As[c + 1][r + rr * 32] = a.y;
                As[c + 2][r + rr * 32] = a.z; As[c + 3][r + rr * 32] = a.w;
            }
        }
        {
            int r = tid >> 4, c = (tid & 15) << 2;
#pragma unroll
            for (int rr = 0; rr < 2; rr++)
                *(float4*)&Bs[r + rr * 8][c] =
                    *(const float4*)(W + (size_t)(k0 + r + rr * 8) * DM + n0 + c);
        }
        __syncthreads();
#pragma unroll
        for (int kk = 0; kk < 16; kk++) {
            float a4[4], b8[8];
            *(float4*)a4 = *(float4*)&As[kk][ty << 2];
            *(float4*)b8 = *(float4*)&Bs[kk][tx << 3];
            *(float4*)(b8 + 4) = *(float4*)&Bs[kk][(tx << 3) + 4];
#pragma unroll
            for (int i = 0; i < 4; i++)
#pragma unroll
                for (int j = 0; j < 8; j++) acc[i][j] += a4[i] * b8[j];
        }
        __syncthreads();
    }

#pragma unroll
    for (int i = 0; i < 4; i++) {
        int m = m0 + (ty << 2) + i;
        float o[8];
#pragma unroll
        for (int j = 0; j < 8; j++) o[j] = acc[i][j] + bias[n0 + (tx << 3) + j];

        if (sel < 3) {
            int b = m >> 11, s = m & (S_LEN - 1), h = n0 >> 6;
            size_t base = ((size_t)((b * NH + h) * S_LEN + s)) * HD + (tx << 3);
            unsigned short hh[8], ll[8];
#pragma unroll
            for (int j = 0; j < 8; j++) {
                __nv_bfloat16 hv = __float2bfloat16(o[j]);
                __nv_bfloat16 lv = __float2bfloat16(o[j] - __bfloat162float(hv));
                hh[j] = __bfloat16_as_ushort(hv);
                ll[j] = __bfloat16_as_ushort(lv);
            }
            *(uint4*)(Dh + base) = *(uint4*)hh;
            *(uint4*)(Dl + base) = *(uint4*)ll;
        } else {
            float* dst = Cout + (size_t)m * DM + n0 + (tx << 3);
            *(float4*)dst = *(float4*)o;
            *(float4*)(dst + 4) = *(float4*)(o + 4);
        }
    }
}

// ===========================================================================
// mma.sync attention. Block = 128 queries, 4 warps (warp = 32 q rows).
// Split-bf16 3-term for QK^T and PV. Soft causal mask: p *= 0.5 future keys.
// smem: Q hi/lo (128x72 bf16 each) + double-buffered K/V hi/lo (64x72 each).
// Padded stride 72 elems (144 B) -> conflict-free ldmatrix.
// ===========================================================================
#define SQH 0
#define SQL 18432
#define SKV 36864
#define KVBUF 36864      // per buffer: KH,KL,VH,VL each 9216 B
#define ATT_SMEM (SKV + 2 * KVBUF)   // 110592

__global__ __launch_bounds__(128) void attn_mma_kernel(const int* __restrict__ ump)
{
    extern __shared__ char smc[];
    const uint32_t sb = smem_u32(smc);
    const int tid = threadIdx.x;
    const int w = tid >> 5, lid = tid & 31;
    const int g = lid >> 3, r8 = lid & 7;      // ldmatrix address groups
    const int bh = blockIdx.y;
    const int q0 = blockIdx.x << 7;
    const int um = *ump;

    const size_t hoff = (size_t)bh * S_LEN * HD;
    const __nv_bfloat16* qh_g = g_qh + hoff + (size_t)q0 * HD;
    const __nv_bfloat16* ql_g = g_ql + hoff + (size_t)q0 * HD;
    const __nv_bfloat16* kv_g[4] = { g_kh + hoff, g_kl + hoff, g_vh + hoff, g_vl + hoff };

    // ---- Q tiles into smem (hi/lo), padded stride 144B ----
#pragma unroll
    for (int i = tid; i < 1024; i += 128) {
        int r = i >> 3, ch = i & 7;
        *(uint4*)(smc + SQH + r * 144 + ch * 16) = *(const uint4*)(qh_g + (size_t)r * 64 + ch * 8);
        *(uint4*)(smc + SQL + r * 144 + ch * 16) = *(const uint4*)(ql_g + (size_t)r * 64 + ch * 8);
    }

    // ---- K/V tile loader (cp.async, 2048 x 16B per tile) ----
    auto load_tile = [&](int kt, int buf) {
        uint32_t base = sb + SKV + buf * KVBUF;
#pragma unroll
        for (int i = tid; i < 2048; i += 128) {
            int mat = i >> 9, rem = i & 511, r = rem >> 3, ch = rem & 7;
            cp16(base + mat * 9216 + r * 144 + ch * 16,
                 kv_g[mat] + (size_t)(kt * 64 + r) * 64 + ch * 8);
        }
    };

    float s[2][8][4], o[2][8][4], ls[2][2];
#pragma unroll
    for (int mt = 0; mt < 2; mt++) {
        ls[mt][0] = 0.f; ls[mt][1] = 0.f;
#pragma unroll
        for (int t = 0; t < 8; t++)
#pragma unroll
            for (int e = 0; e < 4; e++) o[mt][t][e] = 0.f;
    }

    load_tile(0, 0);
    CP_COMMIT();

    for (int kt = 0; kt < 32; kt++) {
        if (kt + 1 < 32) { load_tile(kt + 1, (kt + 1) & 1); CP_COMMIT(); CP_WAIT1(); }
        else             { CP_WAIT0(); }
        __syncthreads();

        const uint32_t kb  = sb + SKV + (kt & 1) * KVBUF;
        const uint32_t skh = kb, skl = kb + 9216, svh = kb + 18432, svl = kb + 27648;

#pragma unroll
        for (int mt = 0; mt < 2; mt++)
#pragma unroll
            for (int t = 0; t < 8; t++)
#pragma unroll
                for (int e = 0; e < 4; e++) s[mt][t][e] = 0.f;

        // ---- QK^T: 4 k16 chunks over d=64 ----
#pragma unroll
        for (int kc = 0; kc < 4; kc++) {
            uint32_t qfh[2][4], qfl[2][4];
#pragma unroll
            for (int mt = 0; mt < 2; mt++) {
                int row = w * 32 + mt * 16 + (g & 1) * 8 + r8;
                int col = kc * 16 + (g >> 1) * 8;
                ldsm4(qfh[mt], sb + SQH + row * 144 + col * 2);
                ldsm4(qfl[mt], sb + SQL + row * 144 + col * 2);
            }
            uint32_t kbh[8][2], kbl[8][2];
#pragma unroll
            for (int gn = 0; gn < 4; gn++) {
                int key = gn * 16 + (g >> 1) * 8 + r8;
                int dcol = kc * 16 + (g & 1) * 8;
                uint32_t r4[4];
                ldsm4(r4, skh + key * 144 + dcol * 2);
                kbh[2*gn][0] = r4[0]; kbh[2*gn][1] = r4[1];
                kbh[2*gn+1][0] = r4[2]; kbh[2*gn+1][1] = r4[3];
                ldsm4(r4, skl + key * 144 + dcol * 2);
                kbl[2*gn][0] = r4[0]; kbl[2*gn][1] = r4[1];
                kbl[2*gn+1][0] = r4[2]; kbl[2*gn+1][1] = r4[3];
            }
#pragma unroll
            for (int mt = 0; mt < 2; mt++)
#pragma unroll
                for (int t = 0; t < 8; t++) {
                    mma_bf16(s[mt][t], qfh[mt], kbh[t]);
                    mma_bf16(s[mt][t], qfh[mt], kbl[t]);
                    mma_bf16(s[mt][t], qfl[mt], kbh[t]);
                }
        }

        // ---- softmax numerator (no max; soft mask = x0.5) ----
        const int k0 = kt << 6;
#pragma unroll
        for (int mt = 0; mt < 2; mt++)
#pragma unroll
            for (int t = 0; t < 8; t++)
#pragma unroll
                for (int e = 0; e < 4; e++) {
                    int col = k0 + t * 8 + 2 * (lid & 3) + (e & 1);
                    int row = q0 + w * 32 + mt * 16 + (lid >> 2) + ((e >> 1) * 8);
                    float p = __expf(s[mt][t][e] * 0.125f);
                    if (um && col > row) p *= 0.5f;
                    s[mt][t][e] = p;
                    ls[mt][e >> 1] += p;
                }

        // ---- PV: 4 k16 chunks over 64 keys ----
#pragma unroll
        for (int kc = 0; kc < 4; kc++) {
            uint32_t pah[2][4], pal[2][4];
#pragma unroll
            for (int mt = 0; mt < 2; mt++) {
                const float* c0 = s[mt][2 * kc];
                const float* c1 = s[mt][2 * kc + 1];
#pragma unroll
                for (int hq = 0; hq < 2; hq++) {
                    const float* cc = hq ? c1 : c0;
                    uint32_t h0 = pack2(cc[0], cc[1]);
                    uint32_t h1 = pack2(cc[2], cc[3]);
                    float2 f0 = unpack2(h0), f1 = unpack2(h1);
                    pah[mt][2*hq]   = h0;
                    pah[mt][2*hq+1] = h1;
                    pal[mt][2*hq]   = pack2(cc[0] - f0.x, cc[1] - f0.y);
                    pal[mt][2*hq+1] = pack2(cc[2] - f1.x, cc[3] - f1.y);
                }
            }
            uint32_t vbh[8][2], vbl[8][2];
#pragma unroll
            for (int gd = 0; gd < 4; gd++) {
                int key = kc * 16 + (g & 1) * 8 + r8;
                int dcol = gd * 16 + (g >> 1) * 8;
                uint32_t r4[4];
                ldsm4t(r4, svh + key * 144 + dcol * 2);
                vbh[2*gd][0] = r4[0]; vbh[2*gd][1] = r4[1];
                vbh[2*gd+1][0] = r4[2]; vbh[2*gd+1][1] = r4[3];
                ldsm4t(r4, svl + key * 144 + dcol * 2);
                vbl[2*gd][0] = r4[0]; vbl[2*gd][1] = r4[1];
                vbl[2*gd+1][0] = r4[2]; vbl[2*gd+1][1] = r4[3];
            }
#pragma unroll
            for (int mt = 0; mt < 2; mt++)
#pragma unroll
                for (int t = 0; t < 8; t++) {
                    mma_bf16(o[mt][t], pah[mt], vbh[t]);
                    mma_bf16(o[mt][t], pah[mt], vbl[t]);
                    mma_bf16(o[mt][t], pal[mt], vbh[t]);
                }
        }
        __syncthreads();
    }

    // ---- epilogue: reduce row sums over quad lanes, normalize, store ----
#pragma unroll
    for (int mt = 0; mt < 2; mt++)
#pragma unroll
        for (int hh = 0; hh < 2; hh++) {
            float v = ls[mt][hh];
            v += __shfl_xor_sync(0xffffffffu, v, 1);
            v += __shfl_xor_sync(0xffffffffu, v, 2);
            ls[mt][hh] = v;
        }

    const int b = bh >> 4, h = bh & 15;
#pragma unroll
    for (int mt = 0; mt < 2; mt++) {
        int row0 = q0 + w * 32 + mt * 16 + (lid >> 2);
        float inv0 = 1.0f / ls[mt][0], inv1 = 1.0f / ls[mt][1];
#pragma unroll
        for (int t = 0; t < 8; t++) {
            int cold = t * 8 + 2 * (lid & 3);
            float2 v0 = make_float2(o[mt][t][0] * inv0, o[mt][t][1] * inv0);
            float2 v1 = make_float2(o[mt][t][2] * inv1, o[mt][t][3] * inv1);
            *(float2*)&g_ao[(size_t)(b * S_LEN + row0) * DM + h * 64 + cold] = v0;
            *(float2*)&g_ao[(size_t)(b * S_LEN + row0 + 8) * DM + h * 64 + cold] = v1;
        }
    }
}

// ===========================================================================
extern "C" void kernel_launch(void* const* d_in, const int* in_sizes, int n_in,
                              void* d_out, int out_size)
{
    (void)in_sizes; (void)n_in; (void)out_size;
    const float* q  = (const float*)d_in[0];
    const float* k  = (const float*)d_in[1];
    const float* v  = (const float*)d_in[2];
    const float* Wq = (const float*)d_in[3];
    const float* bq = (const float*)d_in[4];
    const float* Wk = (const float*)d_in[5];
    const float* bk = (const float*)d_in[6];
    const float* Wv = (const float*)d_in[7];
    const float* bv = (const float*)d_in[8];
    const float* Wo = (const float*)d_in[9];
    const float* bo = (const float*)d_in[10];
    const int* use_mask = (const int*)d_in[11];
    float* out = (float*)d_out;

    cudaFuncSetAttribute(attn_mma_kernel, cudaFuncAttributeMaxDynamicSharedMemorySize,
                         ATT_SMEM);

    dim3 gg(MROWS / 64, DM / 64);   // (64, 16)
    gemm_bias_kernel<<<gg, 128>>>(q, Wq, bq, nullptr, 0);
    gemm_bias_kernel<<<gg, 128>>>(k, Wk, bk, nullptr, 1);
    gemm_bias_kernel<<<gg, 128>>>(v, Wv, bv, nullptr, 2);

    attn_mma_kernel<<<dim3(S_LEN / 128, NB * NH), 128, ATT_SMEM>>>(use_mask);

    gemm_bias_kernel<<<gg, 128>>>(nullptr, Wo, bo, out, 3);
}

// round 9
// speedup vs baseline: 5.9138x; 2.4337x over previous
#include <cuda_runtime.h>
#include <cuda_bf16.h>
#include <cstdint>

#define S_LEN 2048
#define NB 2
#define NH 16
#define HD 64
#define DM 1024
#define MROWS (NB * S_LEN)   // 4096

// bf16 hi/lo splits of raw inputs q,k,v [B,S,D]
__device__ __nv_bfloat16 g_xqh[MROWS*DM], g_xql[MROWS*DM];
__device__ __nv_bfloat16 g_xkh[MROWS*DM], g_xkl[MROWS*DM];
__device__ __nv_bfloat16 g_xvh[MROWS*DM], g_xvl[MROWS*DM];
// bf16 hi/lo splits of weights [D,D]
__device__ __nv_bfloat16 g_wqh[DM*DM], g_wql[DM*DM];
__device__ __nv_bfloat16 g_wkh[DM*DM], g_wkl[DM*DM];
__device__ __nv_bfloat16 g_wvh[DM*DM], g_wvl[DM*DM];
__device__ __nv_bfloat16 g_woh[DM*DM], g_wol[DM*DM];
// bf16 hi/lo projected Q/K/V in [B,H,S,64]
__device__ __nv_bfloat16 g_qh[NB*NH*S_LEN*HD], g_ql[NB*NH*S_LEN*HD];
__device__ __nv_bfloat16 g_kh[NB*NH*S_LEN*HD], g_kl[NB*NH*S_LEN*HD];
__device__ __nv_bfloat16 g_vh[NB*NH*S_LEN*HD], g_vl[NB*NH*S_LEN*HD];
// bf16 hi/lo attention output [B,S,D]
__device__ __nv_bfloat16 g_aoh[MROWS*DM], g_aol[MROWS*DM];

// ===========================================================================
// PTX helpers (sm_80-class: ldmatrix / mma.sync / cp.async)
// ===========================================================================
__device__ __forceinline__ uint32_t smem_u32(const void* p) {
    uint32_t a;
    asm("{ .reg .u64 t; cvta.to.shared.u64 t, %1; cvt.u32.u64 %0, t; }" : "=r"(a) : "l"(p));
    return a;
}
__device__ __forceinline__ void ldsm4(uint32_t r[4], uint32_t a) {
    asm volatile("ldmatrix.sync.aligned.m8n8.x4.shared.b16 {%0,%1,%2,%3}, [%4];"
                 : "=r"(r[0]), "=r"(r[1]), "=r"(r[2]), "=r"(r[3]) : "r"(a));
}
__device__ __forceinline__ void ldsm4t(uint32_t r[4], uint32_t a) {
    asm volatile("ldmatrix.sync.aligned.m8n8.x4.trans.shared.b16 {%0,%1,%2,%3}, [%4];"
                 : "=r"(r[0]), "=r"(r[1]), "=r"(r[2]), "=r"(r[3]) : "r"(a));
}
__device__ __forceinline__ void mma_bf16(float c[4], const uint32_t a[4], const uint32_t b[2]) {
    asm volatile("mma.sync.aligned.m16n8k16.row.col.f32.bf16.bf16.f32 "
                 "{%0,%1,%2,%3}, {%4,%5,%6,%7}, {%8,%9}, {%0,%1,%2,%3};"
                 : "+f"(c[0]), "+f"(c[1]), "+f"(c[2]), "+f"(c[3])
                 : "r"(a[0]), "r"(a[1]), "r"(a[2]), "r"(a[3]), "r"(b[0]), "r"(b[1]));
}
__device__ __forceinline__ void cp16(uint32_t dst, const void* src) {
    asm volatile("cp.async.cg.shared.global [%0], [%1], 16;" :: "r"(dst), "l"(src));
}
#define CP_COMMIT() asm volatile("cp.async.commit_group;" ::: "memory")
#define CP_WAIT0()  asm volatile("cp.async.wait_group 0;" ::: "memory")
#define CP_WAIT1()  asm volatile("cp.async.wait_group 1;" ::: "memory")

// pack2(x,y): .b32 with bf16(x) low, bf16(y) high
__device__ __forceinline__ uint32_t pack2(float x, float y) {
    uint32_t r;
    asm("cvt.rn.bf16x2.f32 %0, %1, %2;" : "=r"(r) : "f"(y), "f"(x));
    return r;
}
__device__ __forceinline__ float2 unpack2(uint32_t r) {
    __nv_bfloat162 b = *reinterpret_cast<__nv_bfloat162*>(&r);
    return __bfloat1622float2(b);
}

// ===========================================================================
// fp32 -> bf16 hi/lo split (elementwise)
// ===========================================================================
__global__ __launch_bounds__(256) void split_kernel(
    const float* __restrict__ src, __nv_bfloat16* __restrict__ dh,
    __nv_bfloat16* __restrict__ dl, int n)
{
    int i = (blockIdx.x * 256 + threadIdx.x) * 4;
    if (i >= n) return;
    float4 v = *(const float4*)(src + i);
    uint32_t h0 = pack2(v.x, v.y), h1 = pack2(v.z, v.w);
    float2 f0 = unpack2(h0), f1 = unpack2(h1);
    uint32_t l0 = pack2(v.x - f0.x, v.y - f0.y);
    uint32_t l1 = pack2(v.z - f1.x, v.w - f1.y);
    uint2 hh = make_uint2(h0, h1), ll = make_uint2(l0, l1);
    *(uint2*)(dh + i) = hh;
    *(uint2*)(dl + i) = ll;
}

// ===========================================================================
// Tensor-core GEMM: C[4096x1024] = A @ W + bias (split-bf16, 3 terms).
// Block 128x128, BK=32, 256 thr (8 warps, warp tile 32x64), double-buffered.
// sel 0/1/2: epilogue scatters bf16 hi/lo into Q/K/V [B,H,S,64].
// sel 3: epilogue writes fp32 to Cout.
// A smem stride 80 B (16B-aligned for cp.async; ldmatrix conflict-free).
// ===========================================================================
#define GA_STR 80      // A smem row stride bytes (32 bf16 = 64B + 16B pad)
#define GW_STR 272     // W smem row stride bytes (128 bf16 + pad)
#define G_AH 0
#define G_AL 10240
#define G_WH 20480
#define G_WL 29184
#define G_STAGE 37888
#define GEMM_SMEM (2 * G_STAGE)   // 75776

__global__ __launch_bounds__(256) void tc_gemm(
    const __nv_bfloat16* __restrict__ Ah, const __nv_bfloat16* __restrict__ Al,
    const __nv_bfloat16* __restrict__ Wh, const __nv_bfloat16* __restrict__ Wl,
    const float* __restrict__ bias, float* __restrict__ Cout, int sel)
{
    extern __shared__ char smc[];
    const uint32_t sb = smem_u32(smc);
    const int tid = threadIdx.x;
    const int w = tid >> 5, lid = tid & 31;
    const int g = lid >> 3, r8 = lid & 7;
    const int wm = w >> 1, wn = w & 1;           // warp grid 4x2
    const int m0 = blockIdx.x << 7, n0 = blockIdx.y << 7;

    __nv_bfloat16 *Dh = nullptr, *Dl = nullptr;
    if (sel == 0) { Dh = g_qh; Dl = g_ql; }
    else if (sel == 1) { Dh = g_kh; Dl = g_kl; }
    else if (sel == 2) { Dh = g_vh; Dl = g_vl; }

    auto load_stage = [&](int k0, int buf) {
        uint32_t base = sb + buf * G_STAGE;
#pragma unroll
        for (int i = tid; i < 1024; i += 256) {      // A hi/lo: 128 rows x 4 chunks
            int half = i >> 9, rem = i & 511;
            int r = rem >> 2, ch = rem & 3;
            const __nv_bfloat16* src = (half ? Al : Ah) + (size_t)(m0 + r) * DM + k0 + ch * 8;
            cp16(base + G_AH + half * 10240 + r * GA_STR + ch * 16, src);
        }
#pragma unroll
        for (int i = tid; i < 1024; i += 256) {      // W hi/lo: 32 rows x 16 chunks
            int half = i >> 9, rem = i & 511;
            int r = rem >> 4, ch = rem & 15;
            const __nv_bfloat16* src = (half ? Wl : Wh) + (size_t)(k0 + r) * DM + n0 + ch * 8;
            cp16(base + G_WH + half * 8704 + r * GW_STR + ch * 16, src);
        }
    };

    float acc[2][8][4];
#pragma unroll
    for (int mt = 0; mt < 2; mt++)
#pragma unroll
        for (int nt = 0; nt < 8; nt++)
#pragma unroll
            for (int e = 0; e < 4; e++) acc[mt][nt][e] = 0.f;

    load_stage(0, 0);
    CP_COMMIT();

    for (int kt = 0; kt < 32; kt++) {
        if (kt + 1 < 32) { load_stage((kt + 1) << 5, (kt + 1) & 1); CP_COMMIT(); CP_WAIT1(); }
        else             { CP_WAIT0(); }
        __syncthreads();

        uint32_t base = sb + (kt & 1) * G_STAGE;
        uint32_t sAh = base + G_AH, sAl = base + G_AL;
        uint32_t sWh = base + G_WH, sWl = base + G_WL;

#pragma unroll
        for (int kc = 0; kc < 2; kc++) {
            uint32_t afh[2][4], afl[2][4];
#pragma unroll
            for (int mt = 0; mt < 2; mt++) {
                int row = wm * 32 + mt * 16 + (g & 1) * 8 + r8;
                int col = kc * 16 + (g >> 1) * 8;
                ldsm4(afh[mt], sAh + row * GA_STR + col * 2);
                ldsm4(afl[mt], sAl + row * GA_STR + col * 2);
            }
            uint32_t bh[8][2], bl[8][2];
#pragma unroll
            for (int gn = 0; gn < 4; gn++) {
                int krow = kc * 16 + (g & 1) * 8 + r8;
                int ncol = wn * 64 + gn * 16 + (g >> 1) * 8;
                uint32_t r4[4];
                ldsm4t(r4, sWh + krow * GW_STR + ncol * 2);
                bh[2*gn][0] = r4[0]; bh[2*gn][1] = r4[1];
                bh[2*gn+1][0] = r4[2]; bh[2*gn+1][1] = r4[3];
                ldsm4t(r4, sWl + krow * GW_STR + ncol * 2);
                bl[2*gn][0] = r4[0]; bl[2*gn][1] = r4[1];
                bl[2*gn+1][0] = r4[2]; bl[2*gn+1][1] = r4[3];
            }
#pragma unroll
            for (int mt = 0; mt < 2; mt++)
#pragma unroll
                for (int nt = 0; nt < 8; nt++) {
                    mma_bf16(acc[mt][nt], afh[mt], bh[nt]);
                    mma_bf16(acc[mt][nt], afh[mt], bl[nt]);
                    mma_bf16(acc[mt][nt], afl[mt], bh[nt]);
                }
        }
        __syncthreads();
    }

    // epilogue
#pragma unroll
    for (int mt = 0; mt < 2; mt++) {
        int row0 = m0 + wm * 32 + mt * 16 + (lid >> 2);
#pragma unroll
        for (int nt = 0; nt < 8; nt++) {
            int col = n0 + wn * 64 + nt * 8 + 2 * (lid & 3);
            float2 b2 = *(const float2*)(bias + col);
            float c0 = acc[mt][nt][0] + b2.x, c1 = acc[mt][nt][1] + b2.y;
            float c2 = acc[mt][nt][2] + b2.x, c3 = acc[mt][nt][3] + b2.y;
            if (sel < 3) {
                int h = col >> 6, d = col & 63;
#pragma unroll
                for (int hq = 0; hq < 2; hq++) {
                    int row = row0 + hq * 8;
                    int b = row >> 11, s = row & (S_LEN - 1);
                    float x = hq ? c2 : c0, y = hq ? c3 : c1;
                    uint32_t hi = pack2(x, y);
                    float2 f = unpack2(hi);
                    uint32_t lo = pack2(x - f.x, y - f.y);
                    size_t idx = ((size_t)((b * NH + h) * S_LEN + s)) * HD + d;
                    *(uint32_t*)(Dh + idx) = hi;
                    *(uint32_t*)(Dl + idx) = lo;
                }
            } else {
                *(float2*)(Cout + (size_t)row0 * DM + col) = make_float2(c0, c1);
                *(float2*)(Cout + (size_t)(row0 + 8) * DM + col) = make_float2(c2, c3);
            }
        }
    }
}

// ===========================================================================
// mma.sync attention (R6 core). Epilogue writes bf16 hi/lo to g_aoh/g_aol.
// ===========================================================================
#define SQH 0
#define SQL 18432
#define SKV 36864
#define KVBUF 36864
#define ATT_SMEM (SKV + 2 * KVBUF)   // 110592

__global__ __launch_bounds__(128) void attn_mma_kernel(const int* __restrict__ ump)
{
    extern __shared__ char smc[];
    const uint32_t sb = smem_u32(smc);
    const int tid = threadIdx.x;
    const int w = tid >> 5, lid = tid & 31;
    const int g = lid >> 3, r8 = lid & 7;
    const int bh = blockIdx.y;
    const int q0 = blockIdx.x << 7;
    const int um = *ump;

    const size_t hoff = (size_t)bh * S_LEN * HD;
    const __nv_bfloat16* qh_g = g_qh + hoff + (size_t)q0 * HD;
    const __nv_bfloat16* ql_g = g_ql + hoff + (size_t)q0 * HD;
    const __nv_bfloat16* kv_g[4] = { g_kh + hoff, g_kl + hoff, g_vh + hoff, g_vl + hoff };

#pragma unroll
    for (int i = tid; i < 1024; i += 128) {
        int r = i >> 3, ch = i & 7;
        *(uint4*)(smc + SQH + r * 144 + ch * 16) = *(const uint4*)(qh_g + (size_t)r * 64 + ch * 8);
        *(uint4*)(smc + SQL + r * 144 + ch * 16) = *(const uint4*)(ql_g + (size_t)r * 64 + ch * 8);
    }

    auto load_tile = [&](int kt, int buf) {
        uint32_t base = sb + SKV + buf * KVBUF;
#pragma unroll
        for (int i = tid; i < 2048; i += 128) {
            int mat = i >> 9, rem = i & 511, r = rem >> 3, ch = rem & 7;
            cp16(base + mat * 9216 + r * 144 + ch * 16,
                 kv_g[mat] + (size_t)(kt * 64 + r) * 64 + ch * 8);
        }
    };

    float s[2][8][4], o[2][8][4], ls[2][2];
#pragma unroll
    for (int mt = 0; mt < 2; mt++) {
        ls[mt][0] = 0.f; ls[mt][1] = 0.f;
#pragma unroll
        for (int t = 0; t < 8; t++)
#pragma unroll
            for (int e = 0; e < 4; e++) o[mt][t][e] = 0.f;
    }

    load_tile(0, 0);
    CP_COMMIT();

    for (int kt = 0; kt < 32; kt++) {
        if (kt + 1 < 32) { load_tile(kt + 1, (kt + 1) & 1); CP_COMMIT(); CP_WAIT1(); }
        else             { CP_WAIT0(); }
        __syncthreads();

        const uint32_t kb  = sb + SKV + (kt & 1) * KVBUF;
        const uint32_t skh = kb, skl = kb + 9216, svh = kb + 18432, svl = kb + 27648;

#pragma unroll
        for (int mt = 0; mt < 2; mt++)
#pragma unroll
            for (int t = 0; t < 8; t++)
#pragma unroll
                for (int e = 0; e < 4; e++) s[mt][t][e] = 0.f;

#pragma unroll
        for (int kc = 0; kc < 4; kc++) {
            uint32_t qfh[2][4], qfl[2][4];
#pragma unroll
            for (int mt = 0; mt < 2; mt++) {
                int row = w * 32 + mt * 16 + (g & 1) * 8 + r8;
                int col = kc * 16 + (g >> 1) * 8;
                ldsm4(qfh[mt], sb + SQH + row * 144 + col * 2);
                ldsm4(qfl[mt], sb + SQL + row * 144 + col * 2);
            }
            uint32_t kbh[8][2], kbl[8][2];
#pragma unroll
            for (int gn = 0; gn < 4; gn++) {
                int key = gn * 16 + (g >> 1) * 8 + r8;
                int dcol = kc * 16 + (g & 1) * 8;
                uint32_t r4[4];
                ldsm4(r4, skh + key * 144 + dcol * 2);
                kbh[2*gn][0] = r4[0]; kbh[2*gn][1] = r4[1];
                kbh[2*gn+1][0] = r4[2]; kbh[2*gn+1][1] = r4[3];
                ldsm4(r4, skl + key * 144 + dcol * 2);
                kbl[2*gn][0] = r4[0]; kbl[2*gn][1] = r4[1];
                kbl[2*gn+1][0] = r4[2]; kbl[2*gn+1][1] = r4[3];
            }
#pragma unroll
            for (int mt = 0; mt < 2; mt++)
#pragma unroll
                for (int t = 0; t < 8; t++) {
                    mma_bf16(s[mt][t], qfh[mt], kbh[t]);
                    mma_bf16(s[mt][t], qfh[mt], kbl[t]);
                    mma_bf16(s[mt][t], qfl[mt], kbh[t]);
                }
        }

        const int k0 = kt << 6;
#pragma unroll
        for (int mt = 0; mt < 2; mt++)
#pragma unroll
            for (int t = 0; t < 8; t++)
#pragma unroll
                for (int e = 0; e < 4; e++) {
                    int col = k0 + t * 8 + 2 * (lid & 3) + (e & 1);
                    int row = q0 + w * 32 + mt * 16 + (lid >> 2) + ((e >> 1) * 8);
                    float p = __expf(s[mt][t][e] * 0.125f);
                    if (um && col > row) p *= 0.5f;
                    s[mt][t][e] = p;
                    ls[mt][e >> 1] += p;
                }

#pragma unroll
        for (int kc = 0; kc < 4; kc++) {
            uint32_t pah[2][4], pal[2][4];
#pragma unroll
            for (int mt = 0; mt < 2; mt++) {
                const float* c0 = s[mt][2 * kc];
                const float* c1 = s[mt][2 * kc + 1];
#pragma unroll
                for (int hq = 0; hq < 2; hq++) {
                    const float* cc = hq ? c1 : c0;
                    uint32_t h0 = pack2(cc[0], cc[1]);
                    uint32_t h1 = pack2(cc[2], cc[3]);
                    float2 f0 = unpack2(h0), f1 = unpack2(h1);
                    pah[mt][2*hq]   = h0;
                    pah[mt][2*hq+1] = h1;
                    pal[mt][2*hq]   = pack2(cc[0] - f0.x, cc[1] - f0.y);
                    pal[mt][2*hq+1] = pack2(cc[2] - f1.x, cc[3] - f1.y);
                }
            }
            uint32_t vbh[8][2], vbl[8][2];
#pragma unroll
            for (int gd = 0; gd < 4; gd++) {
                int key = kc * 16 + (g & 1) * 8 + r8;
                int dcol = gd * 16 + (g >> 1) * 8;
                uint32_t r4[4];
                ldsm4t(r4, svh + key * 144 + dcol * 2);
                vbh[2*gd][0] = r4[0]; vbh[2*gd][1] = r4[1];
                vbh[2*gd+1][0] = r4[2]; vbh[2*gd+1][1] = r4[3];
                ldsm4t(r4, svl + key * 144 + dcol * 2);
                vbl[2*gd][0] = r4[0]; vbl[2*gd][1] = r4[1];
                vbl[2*gd+1][0] = r4[2]; vbl[2*gd+1][1] = r4[3];
            }
#pragma unroll
            for (int mt = 0; mt < 2; mt++)
#pragma unroll
                for (int t = 0; t < 8; t++) {
                    mma_bf16(o[mt][t], pah[mt], vbh[t]);
                    mma_bf16(o[mt][t], pah[mt], vbl[t]);
                    mma_bf16(o[mt][t], pal[mt], vbh[t]);
                }
        }
        __syncthreads();
    }

#pragma unroll
    for (int mt = 0; mt < 2; mt++)
#pragma unroll
        for (int hh = 0; hh < 2; hh++) {
            float v = ls[mt][hh];
            v += __shfl_xor_sync(0xffffffffu, v, 1);
            v += __shfl_xor_sync(0xffffffffu, v, 2);
            ls[mt][hh] = v;
        }

    const int b = bh >> 4, h = bh & 15;
#pragma unroll
    for (int mt = 0; mt < 2; mt++) {
        int row0 = q0 + w * 32 + mt * 16 + (lid >> 2);
        float inv0 = 1.0f / ls[mt][0], inv1 = 1.0f / ls[mt][1];
#pragma unroll
        for (int t = 0; t < 8; t++) {
            int cold = t * 8 + 2 * (lid & 3);
#pragma unroll
            for (int hq = 0; hq < 2; hq++) {
                float x = (hq ? o[mt][t][2] * inv1 : o[mt][t][0] * inv0);
                float y = (hq ? o[mt][t][3] * inv1 : o[mt][t][1] * inv0);
                uint32_t hi = pack2(x, y);
                float2 f = unpack2(hi);
                uint32_t lo = pack2(x - f.x, y - f.y);
                size_t idx = (size_t)(b * S_LEN + row0 + hq * 8) * DM + h * 64 + cold;
                *(uint32_t*)(g_aoh + idx) = hi;
                *(uint32_t*)(g_aol + idx) = lo;
            }
        }
    }
}

// ===========================================================================
extern "C" void kernel_launch(void* const* d_in, const int* in_sizes, int n_in,
                              void* d_out, int out_size)
{
    (void)in_sizes; (void)n_in; (void)out_size;
    const float* q  = (const float*)d_in[0];
    const float* k  = (const float*)d_in[1];
    const float* v  = (const float*)d_in[2];
    const float* Wq = (const float*)d_in[3];
    const float* bq = (const float*)d_in[4];
    const float* Wk = (const float*)d_in[5];
    const float* bk = (const float*)d_in[6];
    const float* Wv = (const float*)d_in[7];
    const float* bv = (const float*)d_in[8];
    const float* Wo = (const float*)d_in[9];
    const float* bo = (const float*)d_in[10];
    const int* use_mask = (const int*)d_in[11];
    float* out = (float*)d_out;

    cudaFuncSetAttribute(attn_mma_kernel, cudaFuncAttributeMaxDynamicSharedMemorySize, ATT_SMEM);
    cudaFuncSetAttribute(tc_gemm, cudaFuncAttributeMaxDynamicSharedMemorySize, GEMM_SMEM);

    __nv_bfloat16 *xqh, *xql, *xkh, *xkl, *xvh, *xvl;
    __nv_bfloat16 *wqh, *wql, *wkh, *wkl, *wvh, *wvl, *woh, *wol, *aoh, *aol;
    cudaGetSymbolAddress((void**)&xqh, g_xqh); cudaGetSymbolAddress((void**)&xql, g_xql);
    cudaGetSymbolAddress((void**)&xkh, g_xkh); cudaGetSymbolAddress((void**)&xkl, g_xkl);
    cudaGetSymbolAddress((void**)&xvh, g_xvh); cudaGetSymbolAddress((void**)&xvl, g_xvl);
    cudaGetSymbolAddress((void**)&wqh, g_wqh); cudaGetSymbolAddress((void**)&wql, g_wql);
    cudaGetSymbolAddress((void**)&wkh, g_wkh); cudaGetSymbolAddress((void**)&wkl, g_wkl);
    cudaGetSymbolAddress((void**)&wvh, g_wvh); cudaGetSymbolAddress((void**)&wvl, g_wvl);
    cudaGetSymbolAddress((void**)&woh, g_woh); cudaGetSymbolAddress((void**)&wol, g_wol);
    cudaGetSymbolAddress((void**)&aoh, g_aoh); cudaGetSymbolAddress((void**)&aol, g_aol);

    const int NIN = MROWS * DM;       // 4M
    const int NW  = DM * DM;          // 1M
    split_kernel<<<NIN / 1024, 256>>>(q,  xqh, xql, NIN);
    split_kernel<<<NIN / 1024, 256>>>(k,  xkh, xkl, NIN);
    split_kernel<<<NIN / 1024, 256>>>(v,  xvh, xvl, NIN);
    split_kernel<<<NW / 1024, 256>>>(Wq, wqh, wql, NW);
    split_kernel<<<NW / 1024, 256>>>(Wk, wkh, wkl, NW);
    split_kernel<<<NW / 1024, 256>>>(Wv, wvh, wvl, NW);
    split_kernel<<<NW / 1024, 256>>>(Wo, woh, wol, NW);

    dim3 gg(MROWS / 128, DM / 128);   // (32, 8)
    tc_gemm<<<gg, 256, GEMM_SMEM>>>(xqh, xql, wqh, wql, bq, nullptr, 0);
    tc_gemm<<<gg, 256, GEMM_SMEM>>>(xkh, xkl, wkh, wkl, bk, nullptr, 1);
    tc_gemm<<<gg, 256, GEMM_SMEM>>>(xvh, xvl, wvh, wvl, bv, nullptr, 2);

    attn_mma_kernel<<<dim3(S_LEN / 128, NB * NH), 128, ATT_SMEM>>>(use_mask);

    tc_gemm<<<gg, 256, GEMM_SMEM>>>(aoh, aol, woh, wol, bo, out, 3);
}